// round 8
// baseline (speedup 1.0000x reference)
#include <cuda_runtime.h>
#include <math.h>

#define FULL_MASK 0xffffffffu
#define DLEV 5

// Global accumulator state (device allocation forbidden; reset by last block -> graph-replay safe)
__device__ float        g_acc   = 0.0f;
__device__ unsigned int g_count = 0;

__device__ __forceinline__ float max4(float4 q) {
    return fmaxf(fmaxf(q.x, q.y), fmaxf(q.z, q.w));
}

// first element of q equal to m -> global element index (slot*4 + j)
__device__ __forceinline__ int first_eq_idx(float4 q, float m, int slot) {
    int j;
    if      (q.x == m) j = 0;
    else if (q.y == m) j = 1;
    else if (q.z == m) j = 2;
    else               j = 3;
    return (slot << 2) + j;
}

// 256 threads = 8 warps; warp w scans tensor (w&1) of row (blockIdx.x*4 + (w>>1)).
// 8192 warps total -> ~55 warps/SM resident (vs 27.7 with one warp/row).
__global__ void __launch_bounds__(256)
hier_loss_kernel(
    const float* __restrict__ y_pred,
    const float* __restrict__ y_true,
    const float* __restrict__ class_weights,
    const int*   __restrict__ path_ids,   // [C, D]
    const int*   __restrict__ path_len,   // [C]
    const int*   __restrict__ sib_start,  // [C, D]
    const int*   __restrict__ sib_size,   // [C, D]
    float* __restrict__ out,
    int B, int C)
{
    const int warp  = threadIdx.x >> 5;
    const int lane  = threadIdx.x & 31;
    const int slot  = warp >> 1;          // 0..3 row slot within block
    const int which = warp & 1;           // 0 = y_pred, 1 = y_true
    const int row   = blockIdx.x * 4 + slot;

    __shared__ int s_top[4][2];           // [slot][which] -> argmax index

    if (row < B) {
        const float* src = (which ? y_true : y_pred) + (size_t)row * C;
        const float4* s4 = reinterpret_cast<const float4*>(src);
        const int n4 = C >> 2;            // 682 for C=2728

        // ---- pass 1: values-only max, 4 independent trackers, front-batched loads ----
        float v0 = -INFINITY, v1 = -INFINITY, v2 = -INFINITY, v3 = -INFINITY;
        int   sl0 = 0, sl1 = 0, sl2 = 0, sl3 = 0;

        int i = lane;
        for (; i + 96 < n4; i += 128) {
            float4 a0 = s4[i];
            float4 a1 = s4[i + 32];
            float4 a2 = s4[i + 64];
            float4 a3 = s4[i + 96];
            float m0 = max4(a0), m1 = max4(a1), m2 = max4(a2), m3 = max4(a3);
            if (m0 > v0) { v0 = m0; sl0 = i;      }
            if (m1 > v1) { v1 = m1; sl1 = i + 32; }
            if (m2 > v2) { v2 = m2; sl2 = i + 64; }
            if (m3 > v3) { v3 = m3; sl3 = i + 96; }
        }
        for (; i < n4; i += 32) {
            float4 a = s4[i];
            float m = max4(a);
            if (m > v0) { v0 = m; sl0 = i; }
        }
        // scalar remainder with exact indices (none for C=2728; kept for generality)
        float rv = -INFINITY;
        int   ri = 0x7FFFFFFF;
        for (int c = (n4 << 2) + lane; c < C; c += 32) {
            float a = src[c];
            if (a > rv) { rv = a; ri = c; }
        }

        // ---- warp max of values (broadcast) ----
        float w = fmaxf(fmaxf(fmaxf(v0, v1), fmaxf(v2, v3)), rv);
        #pragma unroll
        for (int off = 16; off > 0; off >>= 1)
            w = fmaxf(w, __shfl_xor_sync(FULL_MASK, w, off));

        // ---- pass 2: every tracker holding the max reloads its float4 (L1-hit),
        //      min over candidates = exact first-index tie-break ----
        int cand = 0x7FFFFFFF;
        if (v0 == w) cand = min(cand, first_eq_idx(s4[sl0], w, sl0));
        if (v1 == w) cand = min(cand, first_eq_idx(s4[sl1], w, sl1));
        if (v2 == w) cand = min(cand, first_eq_idx(s4[sl2], w, sl2));
        if (v3 == w) cand = min(cand, first_eq_idx(s4[sl3], w, sl3));
        if (rv == w) cand = min(cand, ri);
        #pragma unroll
        for (int off = 16; off > 0; off >>= 1)
            cand = min(cand, __shfl_xor_sync(FULL_MASK, cand, off));

        if (lane == 0) s_top[slot][which] = cand;
    }
    __syncthreads();

    // ---- tail: warp 0, lanes 0..3 each finish one row; warp-sum; one atomicAdd ----
    if (warp == 0) {
        float row_total = 0.0f;
        const int r = blockIdx.x * 4 + lane;
        if (lane < 4 && r < B) {
            const int pred_top = s_top[lane][0];
            const int true_top = s_top[lane][1];
            const float* prow = y_pred + (size_t)r * C;

            const int len_p = path_len[pred_top];
            const int len_t = path_len[true_top];
            const int lmin  = (len_p < len_t) ? len_p : len_t;
            const int diff  = (len_p > len_t) ? (len_p - len_t) : (len_t - len_p);

            if (diff != 0) {   // else row_total is exactly 0
                float local = 0.0f;
                #pragma unroll
                for (int l = 0; l < DLEV; l++) {
                    if (l < lmin) {
                        const int start = sib_start[true_top * DLEV + l];
                        const int size  = sib_size [true_top * DLEV + l];
                        const int tid_l = path_ids [true_top * DLEV + l];

                        // lse of (y_pred * 0/1 mask): masked-out classes contribute exp(0)=1
                        float s = (float)(C - size);
                        for (int c = start; c < start + size; c++) {
                            s += expf(prow[c]);      // L2-hot (row just streamed)
                        }
                        const float lse = logf(s);
                        const float ce  = lse - prow[tid_l];
                        const float h   = (float)(len_t - l - 1);
                        local += expf(-0.5f * h) * ce;
                    }
                }
                row_total = local * (1.5f * (float)diff) * class_weights[true_top];
            }
        }

        // sum 4 row totals across warp 0 (inactive lanes contribute 0)
        #pragma unroll
        for (int off = 2; off > 0; off >>= 1)
            row_total += __shfl_xor_sync(FULL_MASK, row_total, off);

        if (lane == 0) {
            atomicAdd(&g_acc, row_total);
            __threadfence();                      // order value-add before counter-add
            unsigned int done = atomicAdd(&g_count, 1u);
            if (done == gridDim.x - 1) {
                __threadfence();                  // acquire
                float total = atomicAdd(&g_acc, 0.0f);   // atomic read at L2
                out[0] = total / (float)B;
                g_acc   = 0.0f;
                g_count = 0;                      // reset for next graph replay
            }
        }
    }
}

extern "C" void kernel_launch(void* const* d_in, const int* in_sizes, int n_in,
                              void* d_out, int out_size)
{
    const float* y_pred        = (const float*)d_in[0];
    const float* y_true        = (const float*)d_in[1];
    const float* class_weights = (const float*)d_in[2];
    const int*   path_ids      = (const int*)  d_in[3];
    const int*   path_len      = (const int*)  d_in[4];
    const int*   sib_start     = (const int*)  d_in[5];
    const int*   sib_size      = (const int*)  d_in[6];

    const int C = in_sizes[2];            // 2728
    const int B = in_sizes[0] / C;        // 4096

    const int blocks = (B + 3) / 4;       // 1024: 4 rows/block, 2 warps per row

    hier_loss_kernel<<<blocks, 256>>>(
        y_pred, y_true, class_weights, path_ids, path_len, sib_start, sib_size,
        (float*)d_out, B, C);
}

// round 9
// speedup vs baseline: 1.1212x; 1.1212x over previous
#include <cuda_runtime.h>
#include <math.h>

#define FULL_MASK 0xffffffffu
#define DLEV 5

// Global accumulator state (device allocation forbidden; reset by last block -> graph-replay safe)
__device__ float        g_acc   = 0.0f;
__device__ unsigned int g_count = 0;

__device__ __forceinline__ float max4(float4 q) {
    return fmaxf(fmaxf(q.x, q.y), fmaxf(q.z, q.w));
}

// first element of q equal to m -> global element index (slot*4 + j)
__device__ __forceinline__ int first_eq_idx(float4 q, float m, int slot) {
    int j;
    if      (q.x == m) j = 0;
    else if (q.y == m) j = 1;
    else if (q.z == m) j = 2;
    else               j = 3;
    return (slot << 2) + j;
}

// 256 threads = 8 warps = 8 rows/block (one warp per row; 512 blocks = one full wave)
__global__ void __launch_bounds__(256)
hier_loss_kernel(
    const float* __restrict__ y_pred,
    const float* __restrict__ y_true,
    const float* __restrict__ class_weights,
    const int*   __restrict__ path_ids,   // [C, D]
    const int*   __restrict__ path_len,   // [C]
    const int*   __restrict__ sib_start,  // [C, D]
    const int*   __restrict__ sib_size,   // [C, D]
    float* __restrict__ out,
    int B, int C)
{
    const int warp = threadIdx.x >> 5;
    const int lane = threadIdx.x & 31;
    const int row  = blockIdx.x * 8 + warp;

    __shared__ float s_part[8];

    float row_total = 0.0f;

    if (row < B) {
        const float* prow = y_pred + (size_t)row * C;
        const float* trow = y_true + (size_t)row * C;
        const int n4 = C >> 2;  // 682 for C=2728
        const float4* p4 = reinterpret_cast<const float4*>(prow);
        const float4* t4 = reinterpret_cast<const float4*>(trow);

        // ---- pass 1: values-only max, 4 trackers/tensor, 8 front-batched LDG.128/lane ----
        float pv0 = -INFINITY, pv1 = -INFINITY, pv2 = -INFINITY, pv3 = -INFINITY;
        float tv0 = -INFINITY, tv1 = -INFINITY, tv2 = -INFINITY, tv3 = -INFINITY;
        int   ps0 = 0, ps1 = 0, ps2 = 0, ps3 = 0;
        int   ts0 = 0, ts1 = 0, ts2 = 0, ts3 = 0;

        int i = lane;
        for (; i + 96 < n4; i += 128) {
            float4 a0 = p4[i];
            float4 a1 = p4[i + 32];
            float4 a2 = p4[i + 64];
            float4 a3 = p4[i + 96];
            float4 b0 = t4[i];
            float4 b1 = t4[i + 32];
            float4 b2 = t4[i + 64];
            float4 b3 = t4[i + 96];
            float ma0 = max4(a0), ma1 = max4(a1), ma2 = max4(a2), ma3 = max4(a3);
            float mb0 = max4(b0), mb1 = max4(b1), mb2 = max4(b2), mb3 = max4(b3);
            if (ma0 > pv0) { pv0 = ma0; ps0 = i;      }
            if (ma1 > pv1) { pv1 = ma1; ps1 = i + 32; }
            if (ma2 > pv2) { pv2 = ma2; ps2 = i + 64; }
            if (ma3 > pv3) { pv3 = ma3; ps3 = i + 96; }
            if (mb0 > tv0) { tv0 = mb0; ts0 = i;      }
            if (mb1 > tv1) { tv1 = mb1; ts1 = i + 32; }
            if (mb2 > tv2) { tv2 = mb2; ts2 = i + 64; }
            if (mb3 > tv3) { tv3 = mb3; ts3 = i + 96; }
        }
        for (; i < n4; i += 32) {
            float4 a = p4[i];
            float4 b = t4[i];
            float ma = max4(a), mb = max4(b);
            if (ma > pv0) { pv0 = ma; ps0 = i; }
            if (mb > tv0) { tv0 = mb; ts0 = i; }
        }
        // scalar remainder with exact indices (none for C=2728; kept for generality)
        float prv = -INFINITY, trv = -INFINITY;
        int   pri = 0x7FFFFFFF, tri = 0x7FFFFFFF;
        for (int c = (n4 << 2) + lane; c < C; c += 32) {
            float a = prow[c];
            float b = trow[c];
            if (a > prv) { prv = a; pri = c; }
            if (b > trv) { trv = b; tri = c; }
        }

        // ---- warp max of values (broadcast) ----
        float wp = fmaxf(fmaxf(fmaxf(pv0, pv1), fmaxf(pv2, pv3)), prv);
        float wt = fmaxf(fmaxf(fmaxf(tv0, tv1), fmaxf(tv2, tv3)), trv);
        #pragma unroll
        for (int off = 16; off > 0; off >>= 1) {
            wp = fmaxf(wp, __shfl_xor_sync(FULL_MASK, wp, off));
            wt = fmaxf(wt, __shfl_xor_sync(FULL_MASK, wt, off));
        }

        // ---- pass 2: trackers holding the max reload one float4 (L1-hit);
        //      min over candidates = exact first-index tie-break ----
        int pcand = 0x7FFFFFFF;
        if (pv0 == wp) pcand = min(pcand, first_eq_idx(p4[ps0], wp, ps0));
        if (pv1 == wp) pcand = min(pcand, first_eq_idx(p4[ps1], wp, ps1));
        if (pv2 == wp) pcand = min(pcand, first_eq_idx(p4[ps2], wp, ps2));
        if (pv3 == wp) pcand = min(pcand, first_eq_idx(p4[ps3], wp, ps3));
        if (prv == wp) pcand = min(pcand, pri);
        int tcand = 0x7FFFFFFF;
        if (tv0 == wt) tcand = min(tcand, first_eq_idx(t4[ts0], wt, ts0));
        if (tv1 == wt) tcand = min(tcand, first_eq_idx(t4[ts1], wt, ts1));
        if (tv2 == wt) tcand = min(tcand, first_eq_idx(t4[ts2], wt, ts2));
        if (tv3 == wt) tcand = min(tcand, first_eq_idx(t4[ts3], wt, ts3));
        if (trv == wt) tcand = min(tcand, tri);
        #pragma unroll
        for (int off = 16; off > 0; off >>= 1) {
            pcand = min(pcand, __shfl_xor_sync(FULL_MASK, pcand, off));
            tcand = min(tcand, __shfl_xor_sync(FULL_MASK, tcand, off));
        }

        if (lane == 0) {
            const int pred_top = pcand;
            const int true_top = tcand;
            const int len_p = path_len[pred_top];
            const int len_t = path_len[true_top];
            const int lmin  = (len_p < len_t) ? len_p : len_t;
            const int diff  = (len_p > len_t) ? (len_p - len_t) : (len_t - len_p);

            if (diff != 0) {   // else row_total is exactly 0
                float local = 0.0f;
                #pragma unroll
                for (int l = 0; l < DLEV; l++) {
                    if (l < lmin) {
                        const int start = sib_start[true_top * DLEV + l];
                        const int size  = sib_size [true_top * DLEV + l];
                        const int tid_l = path_ids [true_top * DLEV + l];

                        // lse of (y_pred * 0/1 mask): masked-out classes contribute exp(0)=1
                        float s = (float)(C - size);
                        for (int c = start; c < start + size; c++) {
                            s += expf(prow[c]);      // L1/L2-hot (row just streamed)
                        }
                        const float lse = logf(s);
                        const float ce  = lse - prow[tid_l];
                        const float h   = (float)(len_t - l - 1);
                        local += expf(-0.5f * h) * ce;
                    }
                }
                row_total = local * (1.5f * (float)diff) * class_weights[true_top];
            }
        }
    }

    // ---- block partial sum (8 values) -> one float atomicAdd ----
    if (lane == 0) s_part[warp] = row_total;
    __syncthreads();

    if (threadIdx.x == 0) {
        float part = 0.0f;
        #pragma unroll
        for (int w = 0; w < 8; w++) part += s_part[w];
        atomicAdd(&g_acc, part);
        __threadfence();                          // order value-add before counter-add
        unsigned int done = atomicAdd(&g_count, 1u);
        if (done == gridDim.x - 1) {
            __threadfence();                      // acquire
            float total = atomicAdd(&g_acc, 0.0f);    // atomic read at L2
            out[0] = total / (float)B;
            g_acc   = 0.0f;
            g_count = 0;                          // reset for next graph replay
        }
    }
}

extern "C" void kernel_launch(void* const* d_in, const int* in_sizes, int n_in,
                              void* d_out, int out_size)
{
    const float* y_pred        = (const float*)d_in[0];
    const float* y_true        = (const float*)d_in[1];
    const float* class_weights = (const float*)d_in[2];
    const int*   path_ids      = (const int*)  d_in[3];
    const int*   path_len      = (const int*)  d_in[4];
    const int*   sib_start     = (const int*)  d_in[5];
    const int*   sib_size      = (const int*)  d_in[6];

    const int C = in_sizes[2];            // 2728
    const int B = in_sizes[0] / C;        // 4096

    const int blocks = (B + 7) / 8;       // 512: 8 rows/block, one warp per row

    hier_loss_kernel<<<blocks, 256>>>(
        y_pred, y_true, class_weights, path_ids, path_len, sib_start, sib_size,
        (float*)d_out, B, C);
}

// round 11
// speedup vs baseline: 1.1984x; 1.0688x over previous
#include <cuda_runtime.h>
#include <math.h>

#define FULL_MASK 0xffffffffu
#define DLEV 5

// Global accumulator state (device allocation forbidden; reset by last block -> graph-replay safe)
__device__ float        g_acc   = 0.0f;
__device__ unsigned int g_count = 0;

// 256-bit load with L2 retention hint (sm_103: evict_last requires v8.b32 form)
__device__ __forceinline__ void ldg256_el(const float* p, float4& lo, float4& hi) {
    unsigned r0, r1, r2, r3, r4, r5, r6, r7;
    asm volatile("ld.global.nc.L2::evict_last.v8.b32 {%0,%1,%2,%3,%4,%5,%6,%7}, [%8];"
                 : "=r"(r0), "=r"(r1), "=r"(r2), "=r"(r3),
                   "=r"(r4), "=r"(r5), "=r"(r6), "=r"(r7)
                 : "l"(p));
    lo.x = __uint_as_float(r0); lo.y = __uint_as_float(r1);
    lo.z = __uint_as_float(r2); lo.w = __uint_as_float(r3);
    hi.x = __uint_as_float(r4); hi.y = __uint_as_float(r5);
    hi.z = __uint_as_float(r6); hi.w = __uint_as_float(r7);
}

__device__ __forceinline__ float max4(float4 q) {
    return fmaxf(fmaxf(q.x, q.y), fmaxf(q.z, q.w));
}

// first element of the 8-float chunk equal to m -> global element index (slot*8 + j)
__device__ __forceinline__ int first_eq_idx8(float4 lo, float4 hi, float m, int slot) {
    int j;
    if      (lo.x == m) j = 0;
    else if (lo.y == m) j = 1;
    else if (lo.z == m) j = 2;
    else if (lo.w == m) j = 3;
    else if (hi.x == m) j = 4;
    else if (hi.y == m) j = 5;
    else if (hi.z == m) j = 6;
    else                j = 7;
    return (slot << 3) + j;
}

// 256 threads = 8 warps = 8 rows/block (one warp per row; 512 blocks = one full wave)
__global__ void __launch_bounds__(256)
hier_loss_kernel(
    const float* __restrict__ y_pred,
    const float* __restrict__ y_true,
    const float* __restrict__ class_weights,
    const int*   __restrict__ path_ids,   // [C, D]
    const int*   __restrict__ path_len,   // [C]
    const int*   __restrict__ sib_start,  // [C, D]
    const int*   __restrict__ sib_size,   // [C, D]
    float* __restrict__ out,
    int B, int C)
{
    const int warp = threadIdx.x >> 5;
    const int lane = threadIdx.x & 31;
    const int row  = blockIdx.x * 8 + warp;

    __shared__ float s_part[8];

    float row_total = 0.0f;

    if (row < B) {
        const float* prow = y_pred + (size_t)row * C;
        const float* trow = y_true + (size_t)row * C;
        const int n8 = C >> 3;  // 341 for C=2728 (exact: 341*8 = 2728)

        // ---- pass 1: values-only max over 32B chunks, 2 trackers/tensor,
        //      evict_last retains the 89MB working set in L2 across graph replays ----
        float pv0 = -INFINITY, pv1 = -INFINITY, tv0 = -INFINITY, tv1 = -INFINITY;
        int   ps0 = 0, ps1 = 0, ts0 = 0, ts1 = 0;

        int i = lane;
        for (; i + 32 < n8; i += 64) {
            float4 a0l, a0h, a1l, a1h, b0l, b0h, b1l, b1h;
            ldg256_el(prow + ((size_t)i << 3),        a0l, a0h);
            ldg256_el(prow + ((size_t)(i + 32) << 3), a1l, a1h);
            ldg256_el(trow + ((size_t)i << 3),        b0l, b0h);
            ldg256_el(trow + ((size_t)(i + 32) << 3), b1l, b1h);
            float ma0 = fmaxf(max4(a0l), max4(a0h));
            float ma1 = fmaxf(max4(a1l), max4(a1h));
            float mb0 = fmaxf(max4(b0l), max4(b0h));
            float mb1 = fmaxf(max4(b1l), max4(b1h));
            if (ma0 > pv0) { pv0 = ma0; ps0 = i;      }
            if (ma1 > pv1) { pv1 = ma1; ps1 = i + 32; }
            if (mb0 > tv0) { tv0 = mb0; ts0 = i;      }
            if (mb1 > tv1) { tv1 = mb1; ts1 = i + 32; }
        }
        for (; i < n8; i += 32) {
            float4 al, ah, bl, bh;
            ldg256_el(prow + ((size_t)i << 3), al, ah);
            ldg256_el(trow + ((size_t)i << 3), bl, bh);
            float ma = fmaxf(max4(al), max4(ah));
            float mb = fmaxf(max4(bl), max4(bh));
            if (ma > pv0) { pv0 = ma; ps0 = i; }
            if (mb > tv0) { tv0 = mb; ts0 = i; }
        }
        // scalar remainder with exact indices (none for C=2728; kept for generality)
        float prv = -INFINITY, trv = -INFINITY;
        int   pri = 0x7FFFFFFF, tri = 0x7FFFFFFF;
        for (int c = (n8 << 3) + lane; c < C; c += 32) {
            float a = prow[c];
            float b = trow[c];
            if (a > prv) { prv = a; pri = c; }
            if (b > trv) { trv = b; tri = c; }
        }

        // ---- warp max of values (broadcast) ----
        float wp = fmaxf(fmaxf(pv0, pv1), prv);
        float wt = fmaxf(fmaxf(tv0, tv1), trv);
        #pragma unroll
        for (int off = 16; off > 0; off >>= 1) {
            wp = fmaxf(wp, __shfl_xor_sync(FULL_MASK, wp, off));
            wt = fmaxf(wt, __shfl_xor_sync(FULL_MASK, wt, off));
        }

        // ---- pass 2: trackers holding the max reload their chunk (L1-hit);
        //      min over candidates = exact first-index tie-break ----
        int pcand = 0x7FFFFFFF;
        if (pv0 == wp) {
            float4 lo, hi; ldg256_el(prow + ((size_t)ps0 << 3), lo, hi);
            pcand = min(pcand, first_eq_idx8(lo, hi, wp, ps0));
        }
        if (pv1 == wp) {
            float4 lo, hi; ldg256_el(prow + ((size_t)ps1 << 3), lo, hi);
            pcand = min(pcand, first_eq_idx8(lo, hi, wp, ps1));
        }
        if (prv == wp) pcand = min(pcand, pri);
        int tcand = 0x7FFFFFFF;
        if (tv0 == wt) {
            float4 lo, hi; ldg256_el(trow + ((size_t)ts0 << 3), lo, hi);
            tcand = min(tcand, first_eq_idx8(lo, hi, wt, ts0));
        }
        if (tv1 == wt) {
            float4 lo, hi; ldg256_el(trow + ((size_t)ts1 << 3), lo, hi);
            tcand = min(tcand, first_eq_idx8(lo, hi, wt, ts1));
        }
        if (trv == wt) tcand = min(tcand, tri);
        #pragma unroll
        for (int off = 16; off > 0; off >>= 1) {
            pcand = min(pcand, __shfl_xor_sync(FULL_MASK, pcand, off));
            tcand = min(tcand, __shfl_xor_sync(FULL_MASK, tcand, off));
        }

        if (lane == 0) {
            const int pred_top = pcand;
            const int true_top = tcand;
            const int len_p = path_len[pred_top];
            const int len_t = path_len[true_top];
            const int lmin  = (len_p < len_t) ? len_p : len_t;
            const int diff  = (len_p > len_t) ? (len_p - len_t) : (len_t - len_p);

            if (diff != 0) {   // else row_total is exactly 0
                float local = 0.0f;
                #pragma unroll
                for (int l = 0; l < DLEV; l++) {
                    if (l < lmin) {
                        const int start = sib_start[true_top * DLEV + l];
                        const int size  = sib_size [true_top * DLEV + l];
                        const int tid_l = path_ids [true_top * DLEV + l];

                        // lse of (y_pred * 0/1 mask): masked-out classes contribute exp(0)=1
                        float s = (float)(C - size);
                        for (int c = start; c < start + size; c++) {
                            s += expf(prow[c]);      // L1/L2-hot (row just streamed)
                        }
                        const float lse = logf(s);
                        const float ce  = lse - prow[tid_l];
                        const float h   = (float)(len_t - l - 1);
                        local += expf(-0.5f * h) * ce;
                    }
                }
                row_total = local * (1.5f * (float)diff) * class_weights[true_top];
            }
        }
    }

    // ---- block partial sum (8 values) -> one float atomicAdd ----
    if (lane == 0) s_part[warp] = row_total;
    __syncthreads();

    if (threadIdx.x == 0) {
        float part = 0.0f;
        #pragma unroll
        for (int w = 0; w < 8; w++) part += s_part[w];
        atomicAdd(&g_acc, part);
        __threadfence();                          // order value-add before counter-add
        unsigned int done = atomicAdd(&g_count, 1u);
        if (done == gridDim.x - 1) {
            __threadfence();                      // acquire
            float total = atomicAdd(&g_acc, 0.0f);    // atomic read at L2
            out[0] = total / (float)B;
            g_acc   = 0.0f;
            g_count = 0;                          // reset for next graph replay
        }
    }
}

extern "C" void kernel_launch(void* const* d_in, const int* in_sizes, int n_in,
                              void* d_out, int out_size)
{
    const float* y_pred        = (const float*)d_in[0];
    const float* y_true        = (const float*)d_in[1];
    const float* class_weights = (const float*)d_in[2];
    const int*   path_ids      = (const int*)  d_in[3];
    const int*   path_len      = (const int*)  d_in[4];
    const int*   sib_start     = (const int*)  d_in[5];
    const int*   sib_size      = (const int*)  d_in[6];

    const int C = in_sizes[2];            // 2728
    const int B = in_sizes[0] / C;        // 4096

    const int blocks = (B + 7) / 8;       // 512: 8 rows/block, one warp per row

    hier_loss_kernel<<<blocks, 256>>>(
        y_pred, y_true, class_weights, path_ids, path_len, sib_start, sib_size,
        (float*)d_out, B, C);
}